// round 13
// baseline (speedup 1.0000x reference)
#include <cuda_runtime.h>

// cost_volumn: out[n,y,x, i*9+j] = (1/128) * sum_c f1[n,y,x,c] * f2[n, y+i-4, x+j-4, c]
// f1,f2: [8,128,256,128] f32 NHWC; out: [8,128,256,81] f32. Zero padding outside.
//
// R4 structure (channel-major swizzled smem, register-window FMA) +:
//  - double-buffered chunk staging (CC=8, 2x106KB): stage(k+1) overlaps compute(k),
//    ONE barrier per chunk instead of serialized stage->sync->compute phases.
//  - strength-reduced staging indices (no div/mod, q loop-invariant).

#define DN 8
#define DH 128
#define DW 256
#define DC 128
#define RAD 4
#define NDX 9
#define NOFF 81

constexpr int YB      = 2;             // output rows per block
constexpr int CC      = 8;             // channels per chunk
constexpr int NCH     = DC / CC;       // 16 chunks
constexpr int PX      = 8;             // pixels per thread
constexpr int THREADS = 576;           // 18 warps; warp=(row,dy), lane=x-group
constexpr int XCOLS   = DW + 2 * RAD;  // 264
constexpr int YROWS   = YB + 2 * RAD;  // 10 f2 rows per block
constexpr int ROWLEN  = 276;           // padded row stride (floats)
constexpr int F2ROWS  = YROWS * CC;    // 80
constexpr int F1OFS   = F2ROWS * ROWLEN;        // float offset of f1 region (22080)
constexpr int BUFFLOATS = (F2ROWS + YB * CC) * ROWLEN;   // 96*276 = 26496
constexpr int SMEM_BYTES = 2 * BUFFLOATS * 4;   // 211,968 B

// XOR swizzle on 16B chunks (proven in R4): conflict-free window LDS + STS scatter.
__device__ __forceinline__ int swzidx(int xc) {
    int j = xc >> 2;
    j ^= (j >> 3) & 7;
    return (j << 2) | (xc & 3);
}
__device__ __forceinline__ int swzchunk4(int j) {
    return (j ^ ((j >> 3) & 7)) << 2;
}

extern __shared__ float smem[];

__global__ __launch_bounds__(THREADS)
void costvol_kernel(const float* __restrict__ f1,
                    const float* __restrict__ f2,
                    float* __restrict__ out)
{
    const int y0  = blockIdx.x * YB;
    const int n   = blockIdx.y;
    const int tid = threadIdx.x;
    const int w   = tid >> 5;
    const int r   = w / NDX;           // output row in block (0..1)
    const int i   = w % NDX;           // dy 0..8
    const int g   = tid & 31;          // x-group: pixels 8g..8g+7

    float* bufs[2] = { smem, smem + BUFFLOATS };

    const int rowPix = (n * DH + y0) * DW;

    // Loop-invariant staging state: t = tid + 576*it, q = t&1 (const), u = t>>1.
    const int q    = tid & 1;
    const int u0   = tid >> 1;               // 0..287
    const int row0 = u0 / XCOLS;             // 0 or 1 (u0<288<528)
    const int xc0  = u0 - row0 * XCOLS;

    // ---- stage one chunk (CC=8 channels) into buffer b ----
    auto stage = [&](int ch, float* b) {
        const int cofs = ch * CC + q * 4;
        int row = row0, xcol = xc0;
        #pragma unroll
        for (int it = 0; it < 11; ++it) {
            if (row < YROWS) {
                // f2 item: logical (row, xcol), y2/x2 with halo offset
                const int y2 = y0 + row - RAD;
                const int x2 = xcol - RAD;
                const bool ok = ((unsigned)y2 < DH) & ((unsigned)x2 < DW);
                float4 v = make_float4(0.f, 0.f, 0.f, 0.f);
                if (ok)
                    v = *reinterpret_cast<const float4*>(
                        f2 + (size_t)((n * DH + y2) * DW + x2) * DC + cofs);
                float* d = b + (row * CC + q * 4) * ROWLEN + swzidx(xcol);
                d[0]          = v.x;
                d[ROWLEN]     = v.y;
                d[2 * ROWLEN] = v.z;
                d[3 * ROWLEN] = v.w;
            } else {
                const int vv = (row - YROWS) * XCOLS + xcol;   // u - 2640
                if (vv < YB * DW) {
                    const int x  = vv & (DW - 1);
                    const int r2 = vv >> 8;
                    const float4 v = *reinterpret_cast<const float4*>(
                        f1 + (size_t)(rowPix + r2 * DW + x) * DC + cofs);
                    float* d = b + F1OFS + (r2 * CC + q * 4) * ROWLEN + swzidx(x);
                    d[0]          = v.x;
                    d[ROWLEN]     = v.y;
                    d[2 * ROWLEN] = v.z;
                    d[3 * ROWLEN] = v.w;
                }
            }
            // u += 288 == XCOLS + 24
            xcol += 24; row += 1;
            if (xcol >= XCOLS) { xcol -= XCOLS; row += 1; }
        }
    };

    // Fixed physical window offsets for this lane.
    const int pw0 = swzchunk4(2 * g + 0);
    const int pw1 = swzchunk4(2 * g + 1);
    const int pw2 = swzchunk4(2 * g + 2);
    const int pw3 = swzchunk4(2 * g + 3);

    float acc[NDX][PX];
    #pragma unroll
    for (int a = 0; a < NDX; ++a)
        #pragma unroll
        for (int b = 0; b < PX; ++b) acc[a][b] = 0.f;

    stage(0, bufs[0]);
    __syncthreads();

    #pragma unroll 1
    for (int k = 0; k < NCH; ++k) {
        if (k + 1 < NCH) stage(k + 1, bufs[(k + 1) & 1]);

        // ---- compute chunk k: 8 channels x 72 FMAs, register-resident window ----
        const float* bw = bufs[k & 1];
        const float* b1 = bw + F1OFS;
        #pragma unroll
        for (int c = 0; c < CC; ++c) {
            const float* r1 = b1 + (r * CC + c) * ROWLEN;
            const float4 a0 = *reinterpret_cast<const float4*>(r1 + pw0);
            const float4 a1 = *reinterpret_cast<const float4*>(r1 + pw1);
            const float* r2 = bw + ((r + i) * CC + c) * ROWLEN;
            const float4 w0 = *reinterpret_cast<const float4*>(r2 + pw0);
            const float4 w1 = *reinterpret_cast<const float4*>(r2 + pw1);
            const float4 w2 = *reinterpret_cast<const float4*>(r2 + pw2);
            const float4 w3 = *reinterpret_cast<const float4*>(r2 + pw3);
            const float a[PX]  = {a0.x, a0.y, a0.z, a0.w, a1.x, a1.y, a1.z, a1.w};
            const float wv[16] = {w0.x, w0.y, w0.z, w0.w, w1.x, w1.y, w1.z, w1.w,
                                  w2.x, w2.y, w2.z, w2.w, w3.x, w3.y, w3.z, w3.w};
            #pragma unroll
            for (int dx = 0; dx < NDX; ++dx)
                #pragma unroll
                for (int p = 0; p < PX; ++p)
                    acc[dx][p] = fmaf(a[p], wv[p + dx], acc[dx][p]);
        }
        __syncthreads();   // all warps: done staging k+1, done reading buf k
    }

    // ---- epilogue: contiguous per-block output region ----
    const float inv = 1.0f / (float)DC;
    const int pixBase = rowPix + r * DW + g * PX;
    #pragma unroll
    for (int p = 0; p < PX; ++p) {
        const int ob = (pixBase + p) * NOFF + i * NDX;
        #pragma unroll
        for (int dx = 0; dx < NDX; ++dx)
            out[ob + dx] = acc[dx][p] * inv;
    }
}

extern "C" void kernel_launch(void* const* d_in, const int* in_sizes, int n_in,
                              void* d_out, int out_size)
{
    const float* f1 = (const float*)d_in[0];
    const float* f2 = (const float*)d_in[1];
    float* out      = (float*)d_out;

    cudaFuncSetAttribute(costvol_kernel,
                         cudaFuncAttributeMaxDynamicSharedMemorySize, SMEM_BYTES);
    dim3 grid(DH / YB, DN);  // y fastest -> adjacent blocks share f2 halo in L2
    costvol_kernel<<<grid, THREADS, SMEM_BYTES>>>(f1, f2, out);
}

// round 14
// speedup vs baseline: 5.1356x; 5.1356x over previous
#include <cuda_runtime.h>

// cost_volumn: out[n,y,x, i*9+j] = (1/128) * sum_c f1[n,y,x,c] * f2[n, y+i-4, x+j-4, c]
// f1,f2: [8,128,256,128] f32 NHWC; out: [8,128,256,81] f32. Zero padding outside.
//
// R4 structure (channel-major swizzled smem, register-window FMA, proven 519us)
// with ONE change: CC=8 + double-buffered staging so stage(k+1) overlaps compute(k).
// Spill guards: explicit __launch_bounds__(.,1) (113-reg budget), no pointer arrays.

#define DN 8
#define DH 128
#define DW 256
#define DC 128
#define RAD 4
#define NDX 9
#define NOFF 81

constexpr int YB      = 2;             // output rows per block
constexpr int CC      = 8;             // channels per chunk
constexpr int NCH     = DC / CC;       // 16 chunks
constexpr int PX      = 8;             // pixels per thread
constexpr int THREADS = 576;           // 18 warps; warp=(row,dy), lane=x-group
constexpr int XCOLS   = DW + 2 * RAD;  // 264
constexpr int YROWS   = YB + 2 * RAD;  // 10 f2 rows per block
constexpr int ROWLEN  = 276;           // padded row stride (floats)
constexpr int F2ROWS  = YROWS * CC;    // 80
constexpr int F1OFS   = F2ROWS * ROWLEN;                 // f1 region offset (floats)
constexpr int BUFFLOATS = (F2ROWS + YB * CC) * ROWLEN;   // 96*276 = 26496
constexpr int SMEM_BYTES = 2 * BUFFLOATS * 4;            // 211,968 B

constexpr int F2ITEMS  = YROWS * XCOLS * (CC / 4);       // 5280 float4 items
constexpr int TOTITEMS = F2ITEMS + YB * DW * (CC / 4);   // 6304

// XOR swizzle on 16B chunks (proven): conflict-free window LDS + STS scatter.
__device__ __forceinline__ int swzidx(int xc) {
    int j = xc >> 2;
    j ^= (j >> 3) & 7;
    return (j << 2) | (xc & 3);
}
__device__ __forceinline__ int swzchunk4(int j) {
    return (j ^ ((j >> 3) & 7)) << 2;
}

extern __shared__ float smem[];

__global__ __launch_bounds__(THREADS, 1)
void costvol_kernel(const float* __restrict__ f1,
                    const float* __restrict__ f2,
                    float* __restrict__ out)
{
    const int y0  = blockIdx.x * YB;
    const int n   = blockIdx.y;
    const int tid = threadIdx.x;
    const int w   = tid >> 5;
    const int r   = w / NDX;           // output row in block (0..1)
    const int i   = w % NDX;           // dy 0..8
    const int g   = tid & 31;          // x-group: pixels 8g..8g+7

    float* buf0 = smem;
    float* buf1 = smem + BUFFLOATS;

    const int rowPix = (n * DH + y0) * DW;

    // ---- stage one chunk (CC=8 channels) into buffer b (R4-proven index math) ----
    auto stage = [&](int ch, float* b) {
        const int cofs = ch * CC;
        for (int t = tid; t < TOTITEMS; t += THREADS) {
            if (t < F2ITEMS) {
                const int half = t & 1;                  // channel quad
                const unsigned u = (unsigned)t >> 1;
                const int xcol = (int)(u % (unsigned)XCOLS);
                const int row  = (int)(u / (unsigned)XCOLS);
                const int y2 = y0 + row - RAD;
                const int x2 = xcol - RAD;
                float4 v = make_float4(0.f, 0.f, 0.f, 0.f);
                if (((unsigned)y2 < DH) & ((unsigned)x2 < DW))
                    v = *reinterpret_cast<const float4*>(
                        f2 + (size_t)((n * DH + y2) * DW + x2) * DC + cofs + half * 4);
                float* d = b + (row * CC + half * 4) * ROWLEN + swzidx(xcol);
                d[0]          = v.x;
                d[ROWLEN]     = v.y;
                d[2 * ROWLEN] = v.z;
                d[3 * ROWLEN] = v.w;
            } else {
                const int t2   = t - F2ITEMS;
                const int half = t2 & 1;
                const int u    = t2 >> 1;                // 0..511
                const int x    = u & (DW - 1);
                const int r2   = u >> 8;
                const float4 v = *reinterpret_cast<const float4*>(
                    f1 + (size_t)(rowPix + r2 * DW + x) * DC + cofs + half * 4);
                float* d = b + F1OFS + (r2 * CC + half * 4) * ROWLEN + swzidx(x);
                d[0]          = v.x;
                d[ROWLEN]     = v.y;
                d[2 * ROWLEN] = v.z;
                d[3 * ROWLEN] = v.w;
            }
        }
    };

    // Fixed physical window offsets for this lane.
    const int pw0 = swzchunk4(2 * g + 0);
    const int pw1 = swzchunk4(2 * g + 1);
    const int pw2 = swzchunk4(2 * g + 2);
    const int pw3 = swzchunk4(2 * g + 3);

    float acc[NDX][PX];
    #pragma unroll
    for (int a = 0; a < NDX; ++a)
        #pragma unroll
        for (int b = 0; b < PX; ++b) acc[a][b] = 0.f;

    stage(0, buf0);
    __syncthreads();

    #pragma unroll 1
    for (int k = 0; k < NCH; ++k) {
        if (k + 1 < NCH) stage(k + 1, (k & 1) ? buf0 : buf1);

        // ---- compute chunk k: 8 channels x 72 FMAs, register-resident window ----
        const float* bw = (k & 1) ? buf1 : buf0;
        const float* b1 = bw + F1OFS;
        #pragma unroll
        for (int c = 0; c < CC; ++c) {
            const float* r1 = b1 + (r * CC + c) * ROWLEN;
            const float4 a0 = *reinterpret_cast<const float4*>(r1 + pw0);
            const float4 a1 = *reinterpret_cast<const float4*>(r1 + pw1);
            const float* r2 = bw + ((r + i) * CC + c) * ROWLEN;
            const float4 w0 = *reinterpret_cast<const float4*>(r2 + pw0);
            const float4 w1 = *reinterpret_cast<const float4*>(r2 + pw1);
            const float4 w2 = *reinterpret_cast<const float4*>(r2 + pw2);
            const float4 w3 = *reinterpret_cast<const float4*>(r2 + pw3);
            const float a[PX]  = {a0.x, a0.y, a0.z, a0.w, a1.x, a1.y, a1.z, a1.w};
            const float wv[16] = {w0.x, w0.y, w0.z, w0.w, w1.x, w1.y, w1.z, w1.w,
                                  w2.x, w2.y, w2.z, w2.w, w3.x, w3.y, w3.z, w3.w};
            #pragma unroll
            for (int dx = 0; dx < NDX; ++dx)
                #pragma unroll
                for (int p = 0; p < PX; ++p)
                    acc[dx][p] = fmaf(a[p], wv[p + dx], acc[dx][p]);
        }
        __syncthreads();   // all warps done: staging k+1 written, buf k consumed
    }

    // ---- epilogue: contiguous per-block output region ----
    const float inv = 1.0f / (float)DC;
    const int pixBase = rowPix + r * DW + g * PX;
    #pragma unroll
    for (int p = 0; p < PX; ++p) {
        const int ob = (pixBase + p) * NOFF + i * NDX;
        #pragma unroll
        for (int dx = 0; dx < NDX; ++dx)
            out[ob + dx] = acc[dx][p] * inv;
    }
}

extern "C" void kernel_launch(void* const* d_in, const int* in_sizes, int n_in,
                              void* d_out, int out_size)
{
    const float* f1 = (const float*)d_in[0];
    const float* f2 = (const float*)d_in[1];
    float* out      = (float*)d_out;

    cudaFuncSetAttribute(costvol_kernel,
                         cudaFuncAttributeMaxDynamicSharedMemorySize, SMEM_BYTES);
    dim3 grid(DH / YB, DN);  // y fastest -> adjacent blocks share f2 halo in L2
    costvol_kernel<<<grid, THREADS, SMEM_BYTES>>>(f1, f2, out);
}